// round 15
// baseline (speedup 1.0000x reference)
#include <cuda_runtime.h>
#include <cuda_fp16.h>

#define NP 10000
#define NR 4096
#define NCHUNK 100
#define PPC 100       // points per chunk == TILE (one smem fill per CTA)
#define TILE 100

typedef unsigned long long ull;
typedef unsigned int u32;

// ---- static scratch (no allocations allowed) ----
__device__ ull    g_pp[NP * 6];      // per point: (x,x),(y,y),(z,z),(pw,pw),(lsf,lsf),pad
__device__ u32    g_cf[NP * 24];     // [pt][c*8+g] = half2(0.5*cf[2g][c], 0.5*cf[2g+1][c])
__device__ float4 g_ro[NR];
__device__ float4 g_dn[NR];
__device__ __half g_shh[NR * 16];    // fp16 SH basis per ray
__device__ float  g_part[5 * NCHUNK * NR];
__device__ float  g_opmean;

__device__ __forceinline__ float fsigmoid(float x) { return __fdividef(1.0f, 1.0f + __expf(-x)); }

// ---- packed f32x2 helpers (sm_103a) ----
__device__ __forceinline__ ull pk2(float a, float b) {
    ull r; asm("mov.b64 %0, {%1, %2};" : "=l"(r) : "f"(a), "f"(b)); return r;
}
__device__ __forceinline__ void fma2(ull& d, ull a, ull b) {
    asm("fma.rn.f32x2 %0, %1, %2, %0;" : "+l"(d) : "l"(a), "l"(b));
}
__device__ __forceinline__ ull fma2n(ull a, ull b, ull c) {
    ull d; asm("fma.rn.f32x2 %0, %1, %2, %3;" : "=l"(d) : "l"(a), "l"(b), "l"(c)); return d;
}
__device__ __forceinline__ ull mul2(ull a, ull b) {
    ull d; asm("mul.rn.f32x2 %0, %1, %2;" : "=l"(d) : "l"(a), "l"(b)); return d;
}
__device__ __forceinline__ ull add2(ull a, ull b) {
    ull d; asm("add.rn.f32x2 %0, %1, %2;" : "=l"(d) : "l"(a), "l"(b)); return d;
}
__device__ __forceinline__ float2 unpk2(ull v) {
    float2 r; asm("mov.b64 {%0, %1}, %2;" : "=f"(r.x), "=f"(r.y) : "l"(v)); return r;
}
__device__ __forceinline__ float ex2fast(float x) {
    float y; asm("ex2.approx.f32 %0, %1;" : "=f"(y) : "f"(x)); return y;
}
__device__ __forceinline__ __half2 tanh2fast(__half2 x) {
    __half2 y;
    asm("tanh.approx.f16x2 %0, %1;" : "=r"(*(u32*)&y) : "r"(*(const u32*)&x));
    return y;
}

// ---- fused prep: coeffs + points + rays + opacity mean, one launch ----
#define PREP_BLOCKS ((NP * 24 + 255) / 256)   // 938
__global__ void prep_all(const float* __restrict__ rays_o,
                         const float* __restrict__ rays_d,
                         const float* __restrict__ positions,
                         const int*   __restrict__ sidx,
                         const float* __restrict__ log_delta,
                         const float* __restrict__ log_sigma,
                         const float* __restrict__ raw_op,
                         const float* __restrict__ shc) {
    __shared__ float red[256];
    int b = blockIdx.x, t = threadIdx.x;
    int gid = b * 256 + t;

    if (gid < NP * 24) {   // fp16 channel-planar half-coefficients
        int pt = gid / 24, w = gid % 24;
        int c = w >> 3, g = w & 7;
        const float* base = shc + (size_t)pt * 48;
        __half2 h = __floats2half2_rn(0.5f * base[(2*g)*3 + c], 0.5f * base[(2*g+1)*3 + c]);
        g_cf[gid] = *(const u32*)&h;
    }
    if (gid < NP) {        // point params, pre-broadcast f32x2 layout
        int s = sidx[gid];
        float delta = __expf(log_delta[s]);
        float sigma = __expf(log_sigma[s]);
        float op    = fsigmoid(raw_op[gid]);
        float pw    = -delta * 1.4426950408889634f;   // -delta*log2(e)
        float lsf   = __log2f(sigma * op);            // fold sigma*op into exponent
        float x = positions[gid*3+0], y = positions[gid*3+1], z = positions[gid*3+2];
        g_pp[gid*6 + 0] = pk2(x, x);
        g_pp[gid*6 + 1] = pk2(y, y);
        g_pp[gid*6 + 2] = pk2(z, z);
        g_pp[gid*6 + 3] = pk2(pw, pw);
        g_pp[gid*6 + 4] = pk2(lsf, lsf);
        g_pp[gid*6 + 5] = 0ULL;
    }
    if (gid < NR) {        // ray params + SH basis
        float ox = rays_o[gid*3+0], oy = rays_o[gid*3+1], oz = rays_o[gid*3+2];
        float dx = rays_d[gid*3+0], dy = rays_d[gid*3+1], dz = rays_d[gid*3+2];
        float inv = rsqrtf(dx*dx + dy*dy + dz*dz);
        float x = dx * inv, y = dy * inv, z = dz * inv;
        g_ro[gid] = make_float4(ox, oy, oz, 0.0f);
        g_dn[gid] = make_float4(x, y, z, 0.0f);
        float sh[16];
        sh[0]  = 0.282095f;
        sh[1]  = 0.488603f * y;
        sh[2]  = 0.488603f * z;
        sh[3]  = 0.488603f * x;
        sh[4]  = 1.092548f * x * y;
        sh[5]  = 1.092548f * y * z;
        sh[6]  = 0.315392f * (3.0f * z * z - 1.0f);
        sh[7]  = 1.092548f * x * z;
        sh[8]  = 0.546274f * (x * x - y * y);
        sh[9]  = 0.590044f * y * (3.0f * x * x - y * y);
        sh[10] = 2.890611f * x * y * z;
        sh[11] = 0.457046f * y * (5.0f * z * z - 1.0f);
        sh[12] = 0.373176f * z * (5.0f * z * z - 3.0f);
        sh[13] = 0.457046f * x * (5.0f * z * z - 1.0f);
        sh[14] = 1.445306f * z * (x * x - y * y);
        sh[15] = 0.590044f * x * (x * x - 3.0f * y * y);
#pragma unroll
        for (int k = 0; k < 16; k++) g_shh[gid*16 + k] = __float2half(sh[k]);
    }
    if (b == PREP_BLOCKS - 1) {   // opacity mean (single block reduction)
        float s = 0.0f;
        for (int i = t; i < NP; i += 256) s += fsigmoid(raw_op[i]);
        red[t] = s;
        __syncthreads();
        for (int o = 128; o > 0; o >>= 1) {
            if (t < o) red[t] += red[t + o];
            __syncthreads();
        }
        if (t == 0) g_opmean = red[0] * (1.0f / (float)NP);
    }
}

// per-ray-pair state: packed consts, fp16 SH, packed accumulators
struct Pair {
    ull nox, noy, noz, ndx, ndy, ndz;
    __half2 sh[16];
    ull S, ad, ar, ag, ab;
};

__device__ __forceinline__ void pair_init(Pair& P, int rA, int rB) {
    float4 oA = g_ro[rA], oB = g_ro[rB];
    float4 dA = g_dn[rA], dB = g_dn[rB];
    P.nox = pk2(-oA.x, -oB.x); P.noy = pk2(-oA.y, -oB.y); P.noz = pk2(-oA.z, -oB.z);
    P.ndx = pk2(-dA.x, -dB.x); P.ndy = pk2(-dA.y, -dB.y); P.ndz = pk2(-dA.z, -dB.z);
#pragma unroll
    for (int k = 0; k < 16; k++)
        P.sh[k] = __halves2half2(g_shh[rA*16 + k], g_shh[rB*16 + k]);
    P.S = 0; P.ad = 0; P.ar = 0; P.ag = 0; P.ab = 0;
}

__device__ __forceinline__ void pair_proc(Pair& P, ulonglong2 pa, ulonglong2 pb,
                                          ulonglong2 pc, const uint4* cf) {
    const ull one_p = 0x3F8000003F800000ULL;   // (1.0f, 1.0f)
    const __half2 half05 = __floats2half2_rn(0.5f, 0.5f);

    ull rx = add2(pa.x, P.nox), ry = add2(pa.y, P.noy), rz = add2(pb.x, P.noz);
    ull d2p = mul2(rx, rx); fma2(d2p, ry, ry); fma2(d2p, rz, rz);
    ull ndt = mul2(rx, P.ndx); fma2(ndt, ry, P.ndy); fma2(ndt, rz, P.ndz);

    float2 d2 = unpk2(d2p);
    ull ri_p = pk2(rsqrtf(d2.x), rsqrtf(d2.y));
    ull dist_p = mul2(d2p, ri_p);
    ull t_p  = fma2n(ndt, ri_p, one_p);        // 1 - dot
    ull t2_p = mul2(t_p, t_p);
    ull arg_p = fma2n(pb.y, t2_p, pc.x);       // pw*t^2 + lsf
    float2 ag2 = unpk2(arg_p);
    ull w_p = mul2(pk2(ex2fast(ag2.x), ex2fast(ag2.y)), ri_p);

    uint4 q0 = cf[0], q1 = cf[1];
    uint4 q2 = cf[2], q3 = cf[3];
    uint4 q4 = cf[4], q5 = cf[5];

    __half2 e0 = __floats2half2_rn(0.f, 0.f), o0 = e0;
    __half2 e1 = e0, o1 = e0, e2 = e0, o2 = e0;
#define CH(acc_e, acc_o, qa, qb)                                          \
    {                                                                      \
        __half2 c;                                                         \
        c = *(const __half2*)&qa.x;                                        \
        acc_e = __hfma2(__low2half2(c),  P.sh[0], acc_e);                  \
        acc_o = __hfma2(__high2half2(c), P.sh[1], acc_o);                  \
        c = *(const __half2*)&qa.y;                                        \
        acc_e = __hfma2(__low2half2(c),  P.sh[2], acc_e);                  \
        acc_o = __hfma2(__high2half2(c), P.sh[3], acc_o);                  \
        c = *(const __half2*)&qa.z;                                        \
        acc_e = __hfma2(__low2half2(c),  P.sh[4], acc_e);                  \
        acc_o = __hfma2(__high2half2(c), P.sh[5], acc_o);                  \
        c = *(const __half2*)&qa.w;                                        \
        acc_e = __hfma2(__low2half2(c),  P.sh[6], acc_e);                  \
        acc_o = __hfma2(__high2half2(c), P.sh[7], acc_o);                  \
        c = *(const __half2*)&qb.x;                                        \
        acc_e = __hfma2(__low2half2(c),  P.sh[8], acc_e);                  \
        acc_o = __hfma2(__high2half2(c), P.sh[9], acc_o);                  \
        c = *(const __half2*)&qb.y;                                        \
        acc_e = __hfma2(__low2half2(c),  P.sh[10], acc_e);                 \
        acc_o = __hfma2(__high2half2(c), P.sh[11], acc_o);                 \
        c = *(const __half2*)&qb.z;                                        \
        acc_e = __hfma2(__low2half2(c),  P.sh[12], acc_e);                 \
        acc_o = __hfma2(__high2half2(c), P.sh[13], acc_o);                 \
        c = *(const __half2*)&qb.w;                                        \
        acc_e = __hfma2(__low2half2(c),  P.sh[14], acc_e);                 \
        acc_o = __hfma2(__high2half2(c), P.sh[15], acc_o);                 \
    }
    CH(e0, o0, q0, q1)
    CH(e1, o1, q2, q3)
    CH(e2, o2, q4, q5)
#undef CH
    __half2 col0 = __hfma2(half05, tanh2fast(__hadd2(e0, o0)), half05);
    __half2 col1 = __hfma2(half05, tanh2fast(__hadd2(e1, o1)), half05);
    __half2 col2 = __hfma2(half05, tanh2fast(__hadd2(e2, o2)), half05);

    float2 c0f = __half22float2(col0);
    float2 c1f = __half22float2(col1);
    float2 c2f = __half22float2(col2);
    P.S  = add2(P.S, w_p);
    fma2(P.ad, w_p, dist_p);
    fma2(P.ar, w_p, pk2(c0f.x, c0f.y));
    fma2(P.ag, w_p, pk2(c1f.x, c1f.y));
    fma2(P.ab, w_p, pk2(c2f.x, c2f.y));
}

__device__ __forceinline__ void pair_write(const Pair& P, int chunk, int rA, int rB) {
    float2 Sf = unpk2(P.S), adf = unpk2(P.ad);
    float2 arf = unpk2(P.ar), agf = unpk2(P.ag), abf = unpk2(P.ab);
    int iA = chunk * NR + rA;
    g_part[0 * NCHUNK * NR + iA] = Sf.x;
    g_part[1 * NCHUNK * NR + iA] = arf.x;
    g_part[2 * NCHUNK * NR + iA] = agf.x;
    g_part[3 * NCHUNK * NR + iA] = abf.x;
    g_part[4 * NCHUNK * NR + iA] = adf.x;
    int iB = chunk * NR + rB;
    g_part[0 * NCHUNK * NR + iB] = Sf.y;
    g_part[1 * NCHUNK * NR + iB] = arf.y;
    g_part[2 * NCHUNK * NR + iB] = agf.y;
    g_part[3 * NCHUNK * NR + iB] = abf.y;
    g_part[4 * NCHUNK * NR + iB] = adf.y;
}

// 128 threads, FOUR rays/thread as two independent (A,B) f32x2/HFMA2 streams.
// Point tile + coefficients read once per iteration, serve 4 rays.
__global__ void __launch_bounds__(128, 4)
main_k() {
    int tid   = threadIdx.x;
    int base  = blockIdx.x * 512 + tid;
    int chunk = blockIdx.y;

    Pair X, Y;
    pair_init(X, base,       base + 128);
    pair_init(Y, base + 256, base + 384);

    __shared__ __align__(16) u32 s_cf[TILE * 24];   // read as uint4
    __shared__ __align__(16) ull s_pp[TILE * 6];    // read as ulonglong2

    int p0 = chunk * PPC;
    {
        const uint4* srcp = (const uint4*)(g_pp + (size_t)p0 * 6);
        uint4* dstp = (uint4*)s_pp;
        for (int i = tid; i < TILE * 3; i += 128) dstp[i] = srcp[i];
        const uint4* src = (const uint4*)(g_cf + (size_t)p0 * 24);
        uint4* dst = (uint4*)s_cf;
        for (int i = tid; i < TILE * 6; i += 128) dst[i] = src[i];
    }
    __syncthreads();

#pragma unroll 2
    for (int j = 0; j < TILE; j++) {
        const ulonglong2* pp = (const ulonglong2*)&s_pp[j * 6];
        ulonglong2 pa = pp[0], pb = pp[1], pc = pp[2];
        const uint4* cf = (const uint4*)&s_cf[j * 24];
        pair_proc(X, pa, pb, pc, cf);
        pair_proc(Y, pa, pb, pc, cf);
    }

    pair_write(X, chunk, base,       base + 128);
    pair_write(Y, chunk, base + 256, base + 384);
}

__global__ void finalize(float* __restrict__ out) {
    int ray = blockIdx.x * 256 + threadIdx.x;
    if (ray >= NR) return;
    float S = 0, ar = 0, ag = 0, ab = 0, ad = 0;
    for (int c = 0; c < NCHUNK; c++) {
        int idx = c * NR + ray;
        S  += g_part[0 * NCHUNK * NR + idx];
        ar += g_part[1 * NCHUNK * NR + idx];
        ag += g_part[2 * NCHUNK * NR + idx];
        ab += g_part[3 * NCHUNK * NR + idx];
        ad += g_part[4 * NCHUNK * NR + idx];
    }
    float inv = __fdividef(1.0f, S + 1e-8f);
    out[ray*3 + 0] = ar * inv;
    out[ray*3 + 1] = ag * inv;
    out[ray*3 + 2] = ab * inv;
    out[3*NR + ray] = ad * inv;   // depth
    out[4*NR + ray] = g_opmean;   // opac (broadcast mean opacity)
}

extern "C" void kernel_launch(void* const* d_in, const int* in_sizes, int n_in,
                              void* d_out, int out_size) {
    const float* rays_o    = (const float*)d_in[0];
    const float* rays_d    = (const float*)d_in[1];
    const float* positions = (const float*)d_in[2];
    const int*   sidx      = (const int*)  d_in[3];
    const float* log_delta = (const float*)d_in[4];
    const float* log_sigma = (const float*)d_in[5];
    const float* raw_op    = (const float*)d_in[6];
    const float* shc       = (const float*)d_in[7];
    float* out = (float*)d_out;

    prep_all<<<PREP_BLOCKS, 256>>>(rays_o, rays_d, positions, sidx,
                                   log_delta, log_sigma, raw_op, shc);
    main_k<<<dim3(NR / 512, NCHUNK), 128>>>();
    finalize<<<NR / 256, 256>>>(out);
}

// round 16
// speedup vs baseline: 1.3079x; 1.3079x over previous
#include <cuda_runtime.h>
#include <cuda_fp16.h>

#define NP 10000
#define NR 4096
#define NCHUNK 80
#define PPC 125       // points per chunk == TILE (one smem fill per CTA)
#define TILE 125

typedef unsigned long long ull;
typedef unsigned int u32;

// ---- static scratch (no allocations allowed) ----
__device__ ull    g_pp[NP * 6];      // per point: (x,x),(y,y),(z,z),(pw,pw),(lsf,lsf),pad
__device__ u32    g_cf[NP * 24];     // [pt][c*8+g] = half2(0.5*cf[2g][c], 0.5*cf[2g+1][c])
__device__ float4 g_ro[NR];
__device__ float4 g_dn[NR];
__device__ __half g_shh[NR * 16];    // fp16 SH basis per ray
__device__ float  g_part[5 * NCHUNK * NR];
__device__ float  g_opmean;

__device__ __forceinline__ float fsigmoid(float x) { return __fdividef(1.0f, 1.0f + __expf(-x)); }

// ---- packed f32x2 helpers (sm_103a) ----
__device__ __forceinline__ ull pk2(float a, float b) {
    ull r; asm("mov.b64 %0, {%1, %2};" : "=l"(r) : "f"(a), "f"(b)); return r;
}
__device__ __forceinline__ void fma2(ull& d, ull a, ull b) {
    asm("fma.rn.f32x2 %0, %1, %2, %0;" : "+l"(d) : "l"(a), "l"(b));
}
__device__ __forceinline__ ull fma2n(ull a, ull b, ull c) {
    ull d; asm("fma.rn.f32x2 %0, %1, %2, %3;" : "=l"(d) : "l"(a), "l"(b), "l"(c)); return d;
}
__device__ __forceinline__ ull mul2(ull a, ull b) {
    ull d; asm("mul.rn.f32x2 %0, %1, %2;" : "=l"(d) : "l"(a), "l"(b)); return d;
}
__device__ __forceinline__ ull add2(ull a, ull b) {
    ull d; asm("add.rn.f32x2 %0, %1, %2;" : "=l"(d) : "l"(a), "l"(b)); return d;
}
__device__ __forceinline__ float2 unpk2(ull v) {
    float2 r; asm("mov.b64 {%0, %1}, %2;" : "=f"(r.x), "=f"(r.y) : "l"(v)); return r;
}
__device__ __forceinline__ float ex2fast(float x) {
    float y; asm("ex2.approx.f32 %0, %1;" : "=f"(y) : "f"(x)); return y;
}
__device__ __forceinline__ __half2 tanh2fast(__half2 x) {
    __half2 y;
    asm("tanh.approx.f16x2 %0, %1;" : "=r"(*(u32*)&y) : "r"(*(const u32*)&x));
    return y;
}

// ---- fused prep: coeffs + points + rays + opacity mean, one launch ----
#define PREP_BLOCKS ((NP * 24 + 255) / 256)   // 938
__global__ void prep_all(const float* __restrict__ rays_o,
                         const float* __restrict__ rays_d,
                         const float* __restrict__ positions,
                         const int*   __restrict__ sidx,
                         const float* __restrict__ log_delta,
                         const float* __restrict__ log_sigma,
                         const float* __restrict__ raw_op,
                         const float* __restrict__ shc) {
    __shared__ float red[256];
    int b = blockIdx.x, t = threadIdx.x;
    int gid = b * 256 + t;

    if (gid < NP * 24) {   // fp16 channel-planar half-coefficients
        int pt = gid / 24, w = gid % 24;
        int c = w >> 3, g = w & 7;
        const float* base = shc + (size_t)pt * 48;
        __half2 h = __floats2half2_rn(0.5f * base[(2*g)*3 + c], 0.5f * base[(2*g+1)*3 + c]);
        g_cf[gid] = *(const u32*)&h;
    }
    if (gid < NP) {        // point params, pre-broadcast f32x2 layout
        int s = sidx[gid];
        float delta = __expf(log_delta[s]);
        float sigma = __expf(log_sigma[s]);
        float op    = fsigmoid(raw_op[gid]);
        float pw    = -delta * 1.4426950408889634f;   // -delta*log2(e)
        float lsf   = __log2f(sigma * op);            // fold sigma*op into exponent
        float x = positions[gid*3+0], y = positions[gid*3+1], z = positions[gid*3+2];
        g_pp[gid*6 + 0] = pk2(x, x);
        g_pp[gid*6 + 1] = pk2(y, y);
        g_pp[gid*6 + 2] = pk2(z, z);
        g_pp[gid*6 + 3] = pk2(pw, pw);
        g_pp[gid*6 + 4] = pk2(lsf, lsf);
        g_pp[gid*6 + 5] = 0ULL;
    }
    if (gid < NR) {        // ray params + SH basis
        float ox = rays_o[gid*3+0], oy = rays_o[gid*3+1], oz = rays_o[gid*3+2];
        float dx = rays_d[gid*3+0], dy = rays_d[gid*3+1], dz = rays_d[gid*3+2];
        float inv = rsqrtf(dx*dx + dy*dy + dz*dz);
        float x = dx * inv, y = dy * inv, z = dz * inv;
        g_ro[gid] = make_float4(ox, oy, oz, 0.0f);
        g_dn[gid] = make_float4(x, y, z, 0.0f);
        float sh[16];
        sh[0]  = 0.282095f;
        sh[1]  = 0.488603f * y;
        sh[2]  = 0.488603f * z;
        sh[3]  = 0.488603f * x;
        sh[4]  = 1.092548f * x * y;
        sh[5]  = 1.092548f * y * z;
        sh[6]  = 0.315392f * (3.0f * z * z - 1.0f);
        sh[7]  = 1.092548f * x * z;
        sh[8]  = 0.546274f * (x * x - y * y);
        sh[9]  = 0.590044f * y * (3.0f * x * x - y * y);
        sh[10] = 2.890611f * x * y * z;
        sh[11] = 0.457046f * y * (5.0f * z * z - 1.0f);
        sh[12] = 0.373176f * z * (5.0f * z * z - 3.0f);
        sh[13] = 0.457046f * x * (5.0f * z * z - 1.0f);
        sh[14] = 1.445306f * z * (x * x - y * y);
        sh[15] = 0.590044f * x * (x * x - 3.0f * y * y);
#pragma unroll
        for (int k = 0; k < 16; k++) g_shh[gid*16 + k] = __float2half(sh[k]);
    }
    if (b == PREP_BLOCKS - 1) {   // opacity mean (single block reduction)
        float s = 0.0f;
        for (int i = t; i < NP; i += 256) s += fsigmoid(raw_op[i]);
        red[t] = s;
        __syncthreads();
        for (int o = 128; o > 0; o >>= 1) {
            if (t < o) red[t] += red[t + o];
            __syncthreads();
        }
        if (t == 0) g_opmean = red[0] * (1.0f / (float)NP);
    }
}

// 128 threads, TWO rays/thread (r0 = blk*256+tid, r1 = r0+128).
// Packed f32x2 pipeline in (rayA, rayB) lanes. Epilog algebra:
//   w*dist == e (exp term), so depth accumulates e directly;
//   colors accumulate T = sum(w*tanh(l/2)); final color = 0.5*(S+T).
__global__ void __launch_bounds__(128, 5)
main_k() {
    int tid   = threadIdx.x;
    int r0    = blockIdx.x * 256 + tid;
    int r1    = r0 + 128;
    int chunk = blockIdx.y;

    float4 oA = g_ro[r0], oB = g_ro[r1];
    float4 dA = g_dn[r0], dB = g_dn[r1];
    ull nox = pk2(-oA.x, -oB.x), noy = pk2(-oA.y, -oB.y), noz = pk2(-oA.z, -oB.z);
    ull ndx = pk2(-dA.x, -dB.x), ndy = pk2(-dA.y, -dB.y), ndz = pk2(-dA.z, -dB.z);
    const ull one_p = 0x3F8000003F800000ULL;   // (1.0f, 1.0f)

    __half2 sh[16];
#pragma unroll
    for (int k = 0; k < 16; k++)
        sh[k] = __halves2half2(g_shh[r0*16 + k], g_shh[r1*16 + k]);

    ull S_p = 0, ad_p = 0, ar_p = 0, ag_p = 0, ab_p = 0;

    __shared__ __align__(16) u32 s_cf[TILE * 24];   // read as uint4
    __shared__ __align__(16) ull s_pp[TILE * 6];    // read as ulonglong2

    int p0 = chunk * PPC;
    {
        const uint4* srcp = (const uint4*)(g_pp + (size_t)p0 * 6);
        uint4* dstp = (uint4*)s_pp;
        for (int i = tid; i < TILE * 3; i += 128) dstp[i] = srcp[i];
        const uint4* src = (const uint4*)(g_cf + (size_t)p0 * 24);
        uint4* dst = (uint4*)s_cf;
        for (int i = tid; i < TILE * 6; i += 128) dst[i] = src[i];
    }
    __syncthreads();

#pragma unroll 2
    for (int j = 0; j < TILE; j++) {
        const ulonglong2* pp = (const ulonglong2*)&s_pp[j * 6];
        ulonglong2 pa = pp[0], pb = pp[1], pc = pp[2];
        // pa = (x,x),(y,y); pb = (z,z),(pw,pw); pc = (lsf,lsf),pad

        // packed geometry (rayA, rayB lanes)
        ull rx = add2(pa.x, nox), ry = add2(pa.y, noy), rz = add2(pb.x, noz);
        ull d2p = mul2(rx, rx); fma2(d2p, ry, ry); fma2(d2p, rz, rz);
        ull ndt = mul2(rx, ndx); fma2(ndt, ry, ndy); fma2(ndt, rz, ndz); // = -(rel.d)

        float2 d2 = unpk2(d2p);
        ull ri_p = pk2(rsqrtf(d2.x), rsqrtf(d2.y));
        ull t_p  = fma2n(ndt, ri_p, one_p);        // 1 - dot
        ull t2_p = mul2(t_p, t_p);
        ull arg_p = fma2n(pb.y, t2_p, pc.x);       // pw*t^2 + lsf
        float2 ag2 = unpk2(arg_p);
        ull e_p = pk2(ex2fast(ag2.x), ex2fast(ag2.y));   // e = w*dist exactly
        ull w_p = mul2(e_p, ri_p);

        // fp16 SH half-logits, lanes = (A,B); even/odd chains per channel
        const uint4* cf = (const uint4*)&s_cf[j * 24];
        uint4 q0 = cf[0], q1 = cf[1];
        uint4 q2 = cf[2], q3 = cf[3];
        uint4 q4 = cf[4], q5 = cf[5];

        __half2 e0 = __floats2half2_rn(0.f,0.f), o0 = e0;
        __half2 e1 = e0, o1 = e0, e2 = e0, o2 = e0;
#define CH(acc_e, acc_o, qa, qb)                                          \
        {                                                                  \
            __half2 c;                                                     \
            c = *(const __half2*)&qa.x;                                    \
            acc_e = __hfma2(__low2half2(c),  sh[0], acc_e);                \
            acc_o = __hfma2(__high2half2(c), sh[1], acc_o);                \
            c = *(const __half2*)&qa.y;                                    \
            acc_e = __hfma2(__low2half2(c),  sh[2], acc_e);                \
            acc_o = __hfma2(__high2half2(c), sh[3], acc_o);                \
            c = *(const __half2*)&qa.z;                                    \
            acc_e = __hfma2(__low2half2(c),  sh[4], acc_e);                \
            acc_o = __hfma2(__high2half2(c), sh[5], acc_o);                \
            c = *(const __half2*)&qa.w;                                    \
            acc_e = __hfma2(__low2half2(c),  sh[6], acc_e);                \
            acc_o = __hfma2(__high2half2(c), sh[7], acc_o);                \
            c = *(const __half2*)&qb.x;                                    \
            acc_e = __hfma2(__low2half2(c),  sh[8], acc_e);                \
            acc_o = __hfma2(__high2half2(c), sh[9], acc_o);                \
            c = *(const __half2*)&qb.y;                                    \
            acc_e = __hfma2(__low2half2(c),  sh[10], acc_e);               \
            acc_o = __hfma2(__high2half2(c), sh[11], acc_o);               \
            c = *(const __half2*)&qb.z;                                    \
            acc_e = __hfma2(__low2half2(c),  sh[12], acc_e);               \
            acc_o = __hfma2(__high2half2(c), sh[13], acc_o);               \
            c = *(const __half2*)&qb.w;                                    \
            acc_e = __hfma2(__low2half2(c),  sh[14], acc_e);               \
            acc_o = __hfma2(__high2half2(c), sh[15], acc_o);               \
        }
        CH(e0, o0, q0, q1)
        CH(e1, o1, q2, q3)
        CH(e2, o2, q4, q5)
#undef CH
        // raw tanh(l/2) per channel; sigmoid affine deferred to finalize
        __half2 th0 = tanh2fast(__hadd2(e0, o0));
        __half2 th1 = tanh2fast(__hadd2(e1, o1));
        __half2 th2 = tanh2fast(__hadd2(e2, o2));

        float2 c0f = __half22float2(th0);
        float2 c1f = __half22float2(th1);
        float2 c2f = __half22float2(th2);
        S_p  = add2(S_p, w_p);
        ad_p = add2(ad_p, e_p);                 // w*dist == e
        fma2(ar_p, w_p, pk2(c0f.x, c0f.y));
        fma2(ag_p, w_p, pk2(c1f.x, c1f.y));
        fma2(ab_p, w_p, pk2(c2f.x, c2f.y));
    }

    float2 Sf = unpk2(S_p), adf = unpk2(ad_p);
    float2 arf = unpk2(ar_p), agf = unpk2(ag_p), abf = unpk2(ab_p);

    int iA = chunk * NR + r0;
    g_part[0 * NCHUNK * NR + iA] = Sf.x;
    g_part[1 * NCHUNK * NR + iA] = arf.x;
    g_part[2 * NCHUNK * NR + iA] = agf.x;
    g_part[3 * NCHUNK * NR + iA] = abf.x;
    g_part[4 * NCHUNK * NR + iA] = adf.x;
    int iB = chunk * NR + r1;
    g_part[0 * NCHUNK * NR + iB] = Sf.y;
    g_part[1 * NCHUNK * NR + iB] = arf.y;
    g_part[2 * NCHUNK * NR + iB] = agf.y;
    g_part[3 * NCHUNK * NR + iB] = abf.y;
    g_part[4 * NCHUNK * NR + iB] = adf.y;
}

__global__ void finalize(float* __restrict__ out) {
    int ray = blockIdx.x * 256 + threadIdx.x;
    if (ray >= NR) return;
    float S = 0, ar = 0, ag = 0, ab = 0, ad = 0;
    for (int c = 0; c < NCHUNK; c++) {
        int idx = c * NR + ray;
        S  += g_part[0 * NCHUNK * NR + idx];
        ar += g_part[1 * NCHUNK * NR + idx];
        ag += g_part[2 * NCHUNK * NR + idx];
        ab += g_part[3 * NCHUNK * NR + idx];
        ad += g_part[4 * NCHUNK * NR + idx];
    }
    float inv = __fdividef(1.0f, S + 1e-8f);
    // color sums were accumulated as T = sum(w*tanh); sigmoid affine here:
    out[ray*3 + 0] = 0.5f * (S + ar) * inv;
    out[ray*3 + 1] = 0.5f * (S + ag) * inv;
    out[ray*3 + 2] = 0.5f * (S + ab) * inv;
    out[3*NR + ray] = ad * inv;   // depth
    out[4*NR + ray] = g_opmean;   // opac (broadcast mean opacity)
}

extern "C" void kernel_launch(void* const* d_in, const int* in_sizes, int n_in,
                              void* d_out, int out_size) {
    const float* rays_o    = (const float*)d_in[0];
    const float* rays_d    = (const float*)d_in[1];
    const float* positions = (const float*)d_in[2];
    const int*   sidx      = (const int*)  d_in[3];
    const float* log_delta = (const float*)d_in[4];
    const float* log_sigma = (const float*)d_in[5];
    const float* raw_op    = (const float*)d_in[6];
    const float* shc       = (const float*)d_in[7];
    float* out = (float*)d_out;

    prep_all<<<PREP_BLOCKS, 256>>>(rays_o, rays_d, positions, sidx,
                                   log_delta, log_sigma, raw_op, shc);
    main_k<<<dim3(NR / 256, NCHUNK), 128>>>();
    finalize<<<NR / 256, 256>>>(out);
}